// round 4
// baseline (speedup 1.0000x reference)
#include <cuda_runtime.h>
#include <math.h>
#include <stdint.h>

// Problem constants
#define SLEN   2048
#define DHEAD  64
#define NGROUP 32          // h*B = 8*4
#define MROWS  8192        // B*S
#define DMODEL 512
#define QK_SCALE 0.04419417382415922f   // 1/sqrt(512)

// Static scratch
__device__ float g_Qhl[(size_t)2 * MROWS * DMODEL];  // interleaved tf32 hi/lo, pre-scaled
__device__ float g_K  [(size_t)MROWS * DMODEL];      // fp32
__device__ float g_Vt [(size_t)MROWS * DMODEL];      // tf32-rounded bits
__device__ float g_O  [(size_t)MROWS * DMODEL];
__device__ float g_Ksum[NGROUP * DHEAD];

// ---------------------------------------------------------------------------
// tf32 helpers
// ---------------------------------------------------------------------------
__device__ __forceinline__ uint32_t f32_to_tf32(float x) {
    uint32_t r;
    asm("cvt.rna.tf32.f32 %0, %1;" : "=r"(r) : "f"(x));
    return r;
}
__device__ __forceinline__ float tf32f(float x) {
    return __uint_as_float(f32_to_tf32(x));
}
__device__ __forceinline__ void mma_tf32(float (&c)[4],
    uint32_t a0, uint32_t a1, uint32_t a2, uint32_t a3,
    uint32_t b0, uint32_t b1)
{
    asm volatile(
        "mma.sync.aligned.m16n8k8.row.col.f32.tf32.tf32.f32 "
        "{%0,%1,%2,%3}, {%4,%5,%6,%7}, {%8,%9}, {%0,%1,%2,%3};\n"
        : "+f"(c[0]), "+f"(c[1]), "+f"(c[2]), "+f"(c[3])
        : "r"(a0), "r"(a1), "r"(a2), "r"(a3), "r"(b0), "r"(b1));
}

// ---------------------------------------------------------------------------
// 3xtf32 tensor-core GEMM: C = A[8192,512] @ W[512,512] + bias, epilogue modes:
//   MODE 0: plain fp32 output
//   MODE 1: t = out*QK_SCALE; write interleaved {tf32hi, tf32lo} (2x size)
//   MODE 2: write tf32-rounded bits
// 128x128 block tile, BK=16, 256 threads, warps 2x4, warp tile 64x32.
// ---------------------------------------------------------------------------
template<int MODE>
__global__ __launch_bounds__(256) void gemm3x(
    const float* __restrict__ A, const float* __restrict__ W,
    const float* __restrict__ bias, float* __restrict__ C)
{
    __shared__ float Ahi[128][20], Alo[128][20];
    __shared__ float Bhi[128][20], Blo[128][20];

    const int tid = threadIdx.x;
    const int bx = blockIdx.x, by = blockIdx.y;
    const int warp = tid >> 5, lane = tid & 31;
    const int wm = warp >> 2, wn = warp & 3;
    const int lg = lane >> 2, la = lane & 3;

    float acc[4][4][4] = {};

    for (int k0 = 0; k0 < DMODEL; k0 += 16) {
        // A tile 128x16, split hi/lo
        #pragma unroll
        for (int l = 0; l < 2; l++) {
            int idx = tid + l * 256;
            int r = idx >> 2, c4 = (idx & 3) * 4;
            float4 v = *(const float4*)(A + (size_t)(by * 128 + r) * DMODEL + k0 + c4);
            float h0 = tf32f(v.x), h1 = tf32f(v.y), h2 = tf32f(v.z), h3 = tf32f(v.w);
            *(float4*)&Ahi[r][c4] = make_float4(h0, h1, h2, h3);
            *(float4*)&Alo[r][c4] = make_float4(tf32f(v.x - h0), tf32f(v.y - h1),
                                                tf32f(v.z - h2), tf32f(v.w - h3));
        }
        // B tile 16x128 transposed to [n][k], split hi/lo
        {
            int k = tid >> 4, nb = tid & 15;
            const float* Wr = W + (size_t)(k0 + k) * DMODEL + bx * 128;
            #pragma unroll
            for (int j = 0; j < 8; j++) {
                int n = nb + 16 * j;
                float b = Wr[n];
                float h = tf32f(b);
                Bhi[n][k] = h;
                Blo[n][k] = tf32f(b - h);
            }
        }
        __syncthreads();

        #pragma unroll
        for (int kk = 0; kk < 2; kk++) {
            uint32_t ahi[4][4], alo[4][4];
            #pragma unroll
            for (int mf = 0; mf < 4; mf++) {
                int r0 = wm * 64 + mf * 16 + lg;
                int c0 = kk * 8 + la;
                ahi[mf][0] = __float_as_uint(Ahi[r0][c0]);
                ahi[mf][1] = __float_as_uint(Ahi[r0 + 8][c0]);
                ahi[mf][2] = __float_as_uint(Ahi[r0][c0 + 4]);
                ahi[mf][3] = __float_as_uint(Ahi[r0 + 8][c0 + 4]);
                alo[mf][0] = __float_as_uint(Alo[r0][c0]);
                alo[mf][1] = __float_as_uint(Alo[r0 + 8][c0]);
                alo[mf][2] = __float_as_uint(Alo[r0][c0 + 4]);
                alo[mf][3] = __float_as_uint(Alo[r0 + 8][c0 + 4]);
            }
            #pragma unroll
            for (int nf = 0; nf < 4; nf++) {
                int n = wn * 32 + nf * 8 + lg;
                int c0 = kk * 8 + la;
                uint32_t bhi0 = __float_as_uint(Bhi[n][c0]);
                uint32_t bhi1 = __float_as_uint(Bhi[n][c0 + 4]);
                uint32_t blo0 = __float_as_uint(Blo[n][c0]);
                uint32_t blo1 = __float_as_uint(Blo[n][c0 + 4]);
                #pragma unroll
                for (int mf = 0; mf < 4; mf++) {
                    mma_tf32(acc[mf][nf], ahi[mf][0], ahi[mf][1], ahi[mf][2], ahi[mf][3], bhi0, bhi1);
                    mma_tf32(acc[mf][nf], alo[mf][0], alo[mf][1], alo[mf][2], alo[mf][3], bhi0, bhi1);
                    mma_tf32(acc[mf][nf], ahi[mf][0], ahi[mf][1], ahi[mf][2], ahi[mf][3], blo0, blo1);
                }
            }
        }
        __syncthreads();
    }

    // epilogue
    #pragma unroll
    for (int mf = 0; mf < 4; mf++) {
        int r0 = by * 128 + wm * 64 + mf * 16 + lg;
        #pragma unroll
        for (int nf = 0; nf < 4; nf++) {
            int c = bx * 128 + wn * 32 + nf * 8 + 2 * la;
            float b0 = bias[c], b1 = bias[c + 1];
            #pragma unroll
            for (int h = 0; h < 2; h++) {           // h=0: rows r0, h=1: r0+8
                int r = r0 + h * 8;
                float t0 = acc[mf][nf][2 * h + 0] + b0;
                float t1 = acc[mf][nf][2 * h + 1] + b1;
                if (MODE == 0) {
                    *(float2*)(C + (size_t)r * DMODEL + c) = make_float2(t0, t1);
                } else if (MODE == 1) {
                    t0 *= QK_SCALE; t1 *= QK_SCALE;
                    float h0 = tf32f(t0), h1 = tf32f(t1);
                    float l0 = tf32f(t0 - h0), l1 = tf32f(t1 - h1);
                    *(float4*)(C + 2 * ((size_t)r * DMODEL + c)) =
                        make_float4(h0, l0, h1, l1);
                } else {
                    *(float2*)(C + (size_t)r * DMODEL + c) =
                        make_float2(tf32f(t0), tf32f(t1));
                }
            }
        }
    }
}

// ---------------------------------------------------------------------------
// Ksum: zero + banded atomic column-sum of K (per group, mod-64 columns)
// ---------------------------------------------------------------------------
__global__ void zero_ksum(float* Ksum) {
    int i = blockIdx.x * 1024 + threadIdx.x;
    if (i < NGROUP * DHEAD) Ksum[i] = 0.f;
}

__global__ __launch_bounds__(256) void kcolsum_kernel(
    const float* __restrict__ K, float* __restrict__ Ksum)
{
    __shared__ float red[256];
    const int g = blockIdx.x, band = blockIdx.y;
    const float* Kg = K + (size_t)g * SLEN * DHEAD;
    const int c = threadIdx.x & 63;
    const int chunk = threadIdx.x >> 6;

    float s = 0.f;
    int rbase = band * 256 + chunk * 64;
    #pragma unroll 4
    for (int r = 0; r < 64; ++r)
        s += Kg[(size_t)(rbase + r) * DHEAD + c];
    red[threadIdx.x] = s;
    __syncthreads();
    if (threadIdx.x < 64)
        atomicAdd(&Ksum[g * DHEAD + threadIdx.x],
                  red[threadIdx.x] + red[64 + threadIdx.x] +
                  red[128 + threadIdx.x] + red[192 + threadIdx.x]);
}

// ---------------------------------------------------------------------------
// Fused attention (group g, 128-query tile), single pass over 16 key-tiles.
// Q comes in as pre-scaled interleaved tf32 hi/lo; V as tf32 bits; K fp32
// (split to hi/lo at use). P stored to smem as tf32 bits (no reload cvt).
// ---------------------------------------------------------------------------
#define QHLP 136
#define KP 72
#define PP 136
#define SMEM_FLOATS (17408 + 9216 + 9216 + 17408 + 64 + 128 + 128)

__global__ __launch_bounds__(256, 1) void fused_attn(
    const float* __restrict__ Qhl, const float* __restrict__ K,
    const float* __restrict__ Vt, const float* __restrict__ Ksum,
    float* __restrict__ O)
{
    extern __shared__ float sm[];
    float* Qs    = sm;                   // [128][136] interleaved hi/lo
    float* Ks    = Qs + 17408;           // [128][72] fp32
    float* Vs    = Ks + 9216;            // [128][72] tf32 bits
    float* Ps    = Vs + 9216;            // [128][136] tf32 bits
    float* s_ksum = Ps + 17408;          // 64
    float* s_mean = s_ksum + 64;         // 128
    float* Zsm    = s_mean + 128;        // 128

    const int tid = threadIdx.x;
    const int lane = tid & 31, warp = tid >> 5;
    const int wm = warp >> 2, wn = warp & 3;     // warp grid 2x4
    const int lg = lane >> 2, la = lane & 3;
    const int g = blockIdx.y, qt = blockIdx.x;

    const float* Qg = Qhl + 2 * ((size_t)g * SLEN * DHEAD + (size_t)qt * 128 * DHEAD);
    const float* Kg = K  + (size_t)g * SLEN * DHEAD;
    const float* Vg = Vt + (size_t)g * SLEN * DHEAD;

    // --- load interleaved Q tile (pure copy: 16384 floats) ---
    #pragma unroll
    for (int l = 0; l < 16; l++) {
        int idx = tid + l * 256;
        int row = idx >> 5, c4 = (idx & 31) * 4;
        *(float4*)(Qs + row * QHLP + c4) = *(const float4*)(Qg + row * 128 + c4);
    }
    if (tid < 64)  s_ksum[tid] = Ksum[g * DHEAD + tid];
    if (tid < 128) Zsm[tid] = 0.f;
    __syncthreads();

    // --- per-row mean threshold ---
    if (tid < 128) {
        float acc = 0.f;
        #pragma unroll
        for (int d = 0; d < 64; d++)
            acc += (Qs[tid * QHLP + 2 * d] + Qs[tid * QHLP + 2 * d + 1]) * s_ksum[d];
        s_mean[tid] = acc * (1.0f / 2048.0f);
    }
    __syncthreads();

    float oacc[4][2][4];
    float Zreg[4][2];
    #pragma unroll
    for (int mf = 0; mf < 4; mf++) {
        Zreg[mf][0] = Zreg[mf][1] = 0.f;
        #pragma unroll
        for (int nf = 0; nf < 2; nf++)
            #pragma unroll
            for (int j = 0; j < 4; j++) oacc[mf][nf][j] = 0.f;
    }

    for (int kt = 0; kt < 16; ++kt) {
        // --- load K (fp32) and V (tf32 bits) tiles [128][64] ---
        #pragma unroll
        for (int l = 0; l < 8; l++) {
            int idx = tid + l * 256;
            int row = idx >> 4, c4 = (idx & 15) * 4;
            size_t goff = ((size_t)(kt * 128 + row)) * DHEAD + c4;
            *(float4*)(Ks + row * KP + c4) = *(const float4*)(Kg + goff);
            *(float4*)(Vs + row * KP + c4) = *(const float4*)(Vg + goff);
        }
        __syncthreads();

        // === S = Q@K^T, 3xtf32 ===
        float sacc[4][4][4];
        #pragma unroll
        for (int mf = 0; mf < 4; mf++)
            #pragma unroll
            for (int nf = 0; nf < 4; nf++)
                #pragma unroll
                for (int j = 0; j < 4; j++) sacc[mf][nf][j] = 0.f;

        #pragma unroll
        for (int kk = 0; kk < 8; ++kk) {
            uint32_t ahi[4][4], alo[4][4];
            #pragma unroll
            for (int mf = 0; mf < 4; mf++) {
                int r0 = wm * 64 + mf * 16 + lg;
                int c0 = kk * 8 + la;
                float2 p0 = *(float2*)(Qs + r0 * QHLP + 2 * c0);
                float2 p1 = *(float2*)(Qs + (r0 + 8) * QHLP + 2 * c0);
                float2 p2 = *(float2*)(Qs + r0 * QHLP + 2 * (c0 + 4));
                float2 p3 = *(float2*)(Qs + (r0 + 8) * QHLP + 2 * (c0 + 4));
                ahi[mf][0] = __float_as_uint(p0.x); alo[mf][0] = __float_as_uint(p0.y);
                ahi[mf][1] = __float_as_uint(p1.x); alo[mf][1] = __float_as_uint(p1.y);
                ahi[mf][2] = __float_as_uint(p2.x); alo[mf][2] = __float_as_uint(p2.y);
                ahi[mf][3] = __float_as_uint(p3.x); alo[mf][3] = __float_as_uint(p3.y);
            }
            #pragma unroll
            for (int nf = 0; nf < 4; nf++) {
                int kr = wn * 32 + nf * 8 + lg;
                int kc = kk * 8 + la;
                float b0f = Ks[kr * KP + kc];
                float b1f = Ks[kr * KP + kc + 4];
                uint32_t bhi0 = f32_to_tf32(b0f);
                uint32_t bhi1 = f32_to_tf32(b1f);
                uint32_t blo0 = f32_to_tf32(b0f - __uint_as_float(bhi0));
                uint32_t blo1 = f32_to_tf32(b1f - __uint_as_float(bhi1));
                #pragma unroll
                for (int mf = 0; mf < 4; mf++) {
                    mma_tf32(sacc[mf][nf], ahi[mf][0], ahi[mf][1], ahi[mf][2], ahi[mf][3], bhi0, bhi1);
                    mma_tf32(sacc[mf][nf], alo[mf][0], alo[mf][1], alo[mf][2], alo[mf][3], bhi0, bhi1);
                    mma_tf32(sacc[mf][nf], ahi[mf][0], ahi[mf][1], ahi[mf][2], ahi[mf][3], blo0, blo1);
                }
            }
        }

        // === mask + exp + store P (tf32 bits) ===
        #pragma unroll
        for (int mf = 0; mf < 4; mf++) {
            int r0 = wm * 64 + mf * 16 + lg;
            float m0 = s_mean[r0], m1 = s_mean[r0 + 8];
            #pragma unroll
            for (int nf = 0; nf < 4; nf++) {
                int col = wn * 32 + nf * 8 + 2 * la;
                float s0 = sacc[mf][nf][0], s1 = sacc[mf][nf][1];
                float s2 = sacc[mf][nf][2], s3 = sacc[mf][nf][3];
                float p0 = (s0 > m0) ? tf32f(__expf(s0)) : 0.f;
                float p1 = (s1 > m0) ? tf32f(__expf(s1)) : 0.f;
                float p2 = (s2 > m1) ? tf32f(__expf(s2)) : 0.f;
                float p3 = (s3 > m1) ? tf32f(__expf(s3)) : 0.f;
                Zreg[mf][0] += p0 + p1;
                Zreg[mf][1] += p2 + p3;
                *(float2*)(Ps + r0 * PP + col)       = make_float2(p0, p1);
                *(float2*)(Ps + (r0 + 8) * PP + col) = make_float2(p2, p3);
            }
        }
        __syncthreads();

        // === O += P @ V (operands already tf32 bits) ===
        #pragma unroll
        for (int kk = 0; kk < 16; ++kk) {
            uint32_t bv[2][2];
            #pragma unroll
            for (int nf = 0; nf < 2; nf++) {
                int vc = wn * 16 + nf * 8 + lg;
                int vr = kk * 8 + la;
                bv[nf][0] = __float_as_uint(Vs[vr * KP + vc]);
                bv[nf][1] = __float_as_uint(Vs[(vr + 4) * KP + vc]);
            }
            #pragma unroll
            for (int mf = 0; mf < 4; mf++) {
                int r0 = wm * 64 + mf * 16 + lg;
                int c0 = kk * 8 + la;
                uint32_t a0 = __float_as_uint(Ps[r0 * PP + c0]);
                uint32_t a1 = __float_as_uint(Ps[(r0 + 8) * PP + c0]);
                uint32_t a2 = __float_as_uint(Ps[r0 * PP + c0 + 4]);
                uint32_t a3 = __float_as_uint(Ps[(r0 + 8) * PP + c0 + 4]);
                mma_tf32(oacc[mf][0], a0, a1, a2, a3, bv[0][0], bv[0][1]);
                mma_tf32(oacc[mf][1], a0, a1, a2, a3, bv[1][0], bv[1][1]);
            }
        }
        __syncthreads();
    }

    // --- Z reduction ---
    #pragma unroll
    for (int mf = 0; mf < 4; mf++)
        #pragma unroll
        for (int h = 0; h < 2; h++) {
            float z = Zreg[mf][h];
            z += __shfl_xor_sync(0xffffffffu, z, 1);
            z += __shfl_xor_sync(0xffffffffu, z, 2);
            if (la == 0)
                atomicAdd(&Zsm[wm * 64 + mf * 16 + h * 8 + lg], z);
        }
    __syncthreads();

    // --- normalize and write O ---
    float* Og = O + ((size_t)g * SLEN + qt * 128) * DHEAD;
    #pragma unroll
    for (int mf = 0; mf < 4; mf++) {
        int r0 = wm * 64 + mf * 16 + lg;
        float iz0 = 1.f / Zsm[r0];
        float iz1 = 1.f / Zsm[r0 + 8];
        #pragma unroll
        for (int nf = 0; nf < 2; nf++) {
            int col = wn * 16 + nf * 8 + 2 * la;
            *(float2*)(Og + (size_t)r0 * DHEAD + col) =
                make_float2(oacc[mf][nf][0] * iz0, oacc[mf][nf][1] * iz0);
            *(float2*)(Og + (size_t)(r0 + 8) * DHEAD + col) =
                make_float2(oacc[mf][nf][2] * iz1, oacc[mf][nf][3] * iz1);
        }
    }
}

// ---------------------------------------------------------------------------
// Launch
// ---------------------------------------------------------------------------
extern "C" void kernel_launch(void* const* d_in, const int* in_sizes, int n_in,
                              void* d_out, int out_size)
{
    const float* x  = (const float*)d_in[0];
    const float* y  = (const float*)d_in[1];
    const float* Wq = (const float*)d_in[2];
    const float* bq = (const float*)d_in[3];
    const float* Wk = (const float*)d_in[4];
    const float* bk = (const float*)d_in[5];
    const float* Wv = (const float*)d_in[6];
    const float* bv = (const float*)d_in[7];
    const float* Wo = (const float*)d_in[8];
    const float* bo = (const float*)d_in[9];
    float* out = (float*)d_out;

    float *Qhlp, *Kp, *Vtp, *Op, *KsumP;
    cudaGetSymbolAddress((void**)&Qhlp, g_Qhl);
    cudaGetSymbolAddress((void**)&Kp, g_K);
    cudaGetSymbolAddress((void**)&Vtp, g_Vt);
    cudaGetSymbolAddress((void**)&Op, g_O);
    cudaGetSymbolAddress((void**)&KsumP, g_Ksum);

    const int smem_bytes = SMEM_FLOATS * 4;
    cudaFuncSetAttribute(fused_attn, cudaFuncAttributeMaxDynamicSharedMemorySize,
                         smem_bytes);

    dim3 gProj(DMODEL / 128, MROWS / 128);  // (4, 64)

    gemm3x<1><<<gProj, 256>>>(x, Wq, bq, Qhlp);   // Q: scaled tf32 hi/lo
    gemm3x<0><<<gProj, 256>>>(y, Wk, bk, Kp);     // K: fp32
    gemm3x<2><<<gProj, 256>>>(y, Wv, bv, Vtp);    // V: tf32 bits

    zero_ksum<<<2, 1024>>>(KsumP);
    kcolsum_kernel<<<dim3(NGROUP, 8), 256>>>(Kp, KsumP);

    fused_attn<<<dim3(16, NGROUP), 256, smem_bytes>>>(Qhlp, Kp, Vtp, KsumP, Op);

    gemm3x<0><<<gProj, 256>>>(Op, Wo, bo, out);   // output projection
}